// round 10
// baseline (speedup 1.0000x reference)
#include <cuda_runtime.h>
#include <cuda_fp16.h>
#include <cstdint>

#define EMB   1024
#define NH    16
#define HD    64
#define BATCH 2
#define SEQ   2048
#define MTOK  (BATCH*SEQ)   // 4096
#define BHN   (BATCH*NH)    // 32

// ---------------- scratch (__device__ globals; no allocs allowed) -----------
__device__ __half g_Xhi[(size_t)MTOK*EMB], g_Xlo[(size_t)MTOK*EMB];
__device__ __half g_Ahi[(size_t)MTOK*EMB], g_Alo[(size_t)MTOK*EMB];
__device__ __half g_Qh[(size_t)MTOK*EMB], g_Ql[(size_t)MTOK*EMB];
__device__ __half g_Kh[(size_t)MTOK*EMB];
__device__ __half g_Vh[(size_t)MTOK*EMB];
__device__ __half g_Wq[(size_t)EMB*EMB], g_Wk[(size_t)EMB*EMB];
__device__ __half g_Wv[(size_t)EMB*EMB], g_Wo[(size_t)EMB*EMB];

// ---------------- helpers ---------------------------------------------------
__device__ __forceinline__ uint32_t smem_u32(const void* p) {
    uint32_t a;
    asm("{ .reg .u64 t; cvta.to.shared.u64 t, %1; cvt.u32.u64 %0, t; }" : "=r"(a) : "l"(p));
    return a;
}
__device__ __forceinline__ void cp16(uint32_t d, const void* s) {
    asm volatile("cp.async.cg.shared.global [%0], [%1], 16;" :: "r"(d), "l"(s));
}
#define CP_COMMIT() asm volatile("cp.async.commit_group;")
#define CP_WAIT(n)  asm volatile("cp.async.wait_group %0;" :: "n"(n))

__device__ __forceinline__ void ldsm4(uint32_t (&r)[4], uint32_t a) {
    asm volatile("ldmatrix.sync.aligned.m8n8.x4.shared.b16 {%0,%1,%2,%3}, [%4];"
        : "=r"(r[0]), "=r"(r[1]), "=r"(r[2]), "=r"(r[3]) : "r"(a));
}
__device__ __forceinline__ void ldsm4t(uint32_t (&r)[4], uint32_t a) {
    asm volatile("ldmatrix.sync.aligned.m8n8.x4.trans.shared.b16 {%0,%1,%2,%3}, [%4];"
        : "=r"(r[0]), "=r"(r[1]), "=r"(r[2]), "=r"(r[3]) : "r"(a));
}
// f32-accumulator HMMA (rt ~8/SMSP)
__device__ __forceinline__ void mma_h(float (&c)[4], const uint32_t (&a)[4], uint32_t b0, uint32_t b1) {
    asm("mma.sync.aligned.m16n8k16.row.col.f32.f16.f16.f32 "
        "{%0,%1,%2,%3}, {%4,%5,%6,%7}, {%8,%9}, {%0,%1,%2,%3};"
        : "+f"(c[0]), "+f"(c[1]), "+f"(c[2]), "+f"(c[3])
        : "r"(a[0]), "r"(a[1]), "r"(a[2]), "r"(a[3]), "r"(b0), "r"(b1));
}
// f16-accumulator HMMA (expected rt ~4/SMSP) — used for small correction terms
__device__ __forceinline__ void mma_hh(uint32_t (&c)[2], const uint32_t (&a)[4], uint32_t b0, uint32_t b1) {
    asm("mma.sync.aligned.m16n8k16.row.col.f16.f16.f16.f16 "
        "{%0,%1}, {%2,%3,%4,%5}, {%6,%7}, {%0,%1};"
        : "+r"(c[0]), "+r"(c[1])
        : "r"(a[0]), "r"(a[1]), "r"(a[2]), "r"(a[3]), "r"(b0), "r"(b1));
}
__device__ __forceinline__ uint32_t packh(float v0, float v1) {
    __half2 h = __floats2half2_rn(v0, v1);
    return *(uint32_t*)&h;
}
__device__ __forceinline__ void split2h(float v0, float v1, uint32_t &hp, uint32_t &lp) {
    __half2 h = __floats2half2_rn(v0, v1);
    hp = *(uint32_t*)&h;
    float h0 = __half2float(__low2half(h));
    float h1 = __half2float(__high2half(h));
    lp = packh(v0 - h0, v1 - h1);
}
__device__ __forceinline__ uint32_t ex2h2(uint32_t x) {
    uint32_t r;
    asm("ex2.approx.f16x2 %0, %1;" : "=r"(r) : "r"(x));
    return r;
}
#define ONESH2 0x3C003C00u   // half2(1.0, 1.0)

// ---------------- fused fp32 -> fp16 split (X hi/lo; W hi only) --------------
__global__ __launch_bounds__(256) void split_all_kernel(
    const float* __restrict__ x,  const float* __restrict__ wq,
    const float* __restrict__ wk, const float* __restrict__ wv,
    const float* __restrict__ wo)
{
    int i = blockIdx.x * 256 + threadIdx.x;
    if (i < 524288) {
        float4 a = ((const float4*)x)[2*i];
        float4 b = ((const float4*)x)[2*i + 1];
        float v[8] = {a.x, a.y, a.z, a.w, b.x, b.y, b.z, b.w};
        uint32_t hp[4], lp[4];
        #pragma unroll
        for (int j = 0; j < 4; j++) split2h(v[2*j], v[2*j+1], hp[j], lp[j]);
        ((uint4*)g_Xhi)[i] = make_uint4(hp[0], hp[1], hp[2], hp[3]);
        ((uint4*)g_Xlo)[i] = make_uint4(lp[0], lp[1], lp[2], lp[3]);
    } else {
        int j = i - 524288;
        int w = j >> 17;
        int off = j & 131071;
        const float* src; __half* hi;
        if (w == 0)      { src = wq; hi = g_Wq; }
        else if (w == 1) { src = wk; hi = g_Wk; }
        else if (w == 2) { src = wv; hi = g_Wv; }
        else             { src = wo; hi = g_Wo; }
        float4 a = ((const float4*)src)[2*off];
        float4 b = ((const float4*)src)[2*off + 1];
        uint32_t hp[4];
        hp[0] = packh(a.x, a.y); hp[1] = packh(a.z, a.w);
        hp[2] = packh(b.x, b.y); hp[3] = packh(b.z, b.w);
        ((uint4*)hi)[off] = make_uint4(hp[0], hp[1], hp[2], hp[3]);
    }
}

// ---------------- GEMM body: 256x128 tile, 256 thr, warp 64x64 --------------
// hi term: f32-acc MMA.  lo term: f16-acc MMA into accl (packed half2 pairs).
#define SPAD   80
#define AL_OFF 20480
#define BH_OFF 40960
#define STG    51200
#define GEMM_SMEM (3*STG)   // 153600
#define NITER (EMB/32)      // 32

__device__ __forceinline__ void gemm_body_256(
    const __half* __restrict__ Ah, const __half* __restrict__ Al,
    const __half* __restrict__ Wh,
    int m0, int n0, float (&acc)[4][8][4], uint32_t (&accl)[4][8][2])
{
    extern __shared__ char sm[];
    const uint32_t smb = smem_u32(sm);
    const int tid = threadIdx.x, lane = tid & 31, wid = tid >> 5;
    const int wm = wid & 3, wn = wid >> 2;

    auto issue = [&](int it) {
        const int k0 = it << 5;
        const uint32_t sb = smb + (uint32_t)(it % 3) * STG;
        #pragma unroll
        for (int j = 0; j < 10; ++j) {
            int idx = tid + (j << 8);
            if (idx < 1024) {
                int row = idx >> 2, seg = idx & 3;
                cp16(sb + row*SPAD + seg*16, Ah + (size_t)(m0 + row)*EMB + k0 + seg*8);
            } else if (idx < 2048) {
                int c = idx - 1024, row = c >> 2, seg = c & 3;
                cp16(sb + AL_OFF + row*SPAD + seg*16, Al + (size_t)(m0 + row)*EMB + k0 + seg*8);
            } else {
                int c = idx - 2048, row = c >> 2, seg = c & 3;
                cp16(sb + BH_OFF + row*SPAD + seg*16, Wh + (size_t)(n0 + row)*EMB + k0 + seg*8);
            }
        }
        CP_COMMIT();
    };

    issue(0); issue(1);
    for (int it = 0; it < NITER; ++it) {
        if (it + 1 < NITER) CP_WAIT(1); else CP_WAIT(0);
        __syncthreads();
        if (it + 2 < NITER) issue(it + 2);
        const uint32_t sb = smb + (uint32_t)(it % 3) * STG;
        #pragma unroll
        for (int ks = 0; ks < 2; ++ks) {
            uint32_t aH[4][4], aL[4][4], bF[4][4];
            uint32_t acol = ks*32 + ((lane>>4)&1)*16;
            #pragma unroll
            for (int mf = 0; mf < 4; ++mf) {
                uint32_t row = wm*64 + mf*16 + ((lane>>3)&1)*8 + (lane&7);
                ldsm4(aH[mf], sb + row*SPAD + acol);
                ldsm4(aL[mf], sb + AL_OFF + row*SPAD + acol);
            }
            #pragma unroll
            for (int ng = 0; ng < 4; ++ng) {
                uint32_t row = wn*64 + ng*16 + ((lane>>4)&1)*8 + (lane&7);
                uint32_t col = ks*32 + ((lane>>3)&1)*16;
                ldsm4(bF[ng], sb + BH_OFF + row*SPAD + col);
            }
            // hi terms: f32 accumulate
            #pragma unroll
            for (int ng = 0; ng < 4; ++ng)
                #pragma unroll
                for (int mf = 0; mf < 4; ++mf) {
                    mma_h(acc[mf][2*ng],   aH[mf], bF[ng][0], bF[ng][1]);
                    mma_h(acc[mf][2*ng+1], aH[mf], bF[ng][2], bF[ng][3]);
                }
            // lo correction terms: f16 accumulate (2x issue rate expected)
            #pragma unroll
            for (int ng = 0; ng < 4; ++ng)
                #pragma unroll
                for (int mf = 0; mf < 4; ++mf) {
                    mma_hh(accl[mf][2*ng],   aL[mf], bF[ng][0], bF[ng][1]);
                    mma_hh(accl[mf][2*ng+1], aL[mf], bF[ng][2], bF[ng][3]);
                }
        }
    }
}

__device__ __forceinline__ float2 lo2f(uint32_t u) {
    return __half22float2(*(__half2*)&u);
}

// ---------------- QKV projection ---------------------------------------------
__global__ void __launch_bounds__(256) qkv_kernel(
    const float* __restrict__ bq, const float* __restrict__ bk, const float* __restrict__ bv)
{
    const __half* Wh; const float* bias;
    __half *dh, *dl; float alpha; int dual;
    if (blockIdx.z == 0)      { Wh = g_Wq; bias = bq; dh = g_Qh; dl = g_Ql; alpha = 0.18033688011112042f; dual = 1; }
    else if (blockIdx.z == 1) { Wh = g_Wk; bias = bk; dh = g_Kh; dl = 0;    alpha = 1.0f; dual = 0; }
    else                      { Wh = g_Wv; bias = bv; dh = g_Vh; dl = 0;    alpha = 1.0f; dual = 0; }

    const int m0 = blockIdx.y << 8, n0 = blockIdx.x << 7;
    float acc[4][8][4] = {};
    uint32_t accl[4][8][2] = {};
    gemm_body_256(g_Xhi, g_Xlo, Wh, m0, n0, acc, accl);

    const int lane = threadIdx.x & 31, wid = threadIdx.x >> 5;
    const int wm = wid & 3, wn = wid >> 2;
    #pragma unroll
    for (int mf = 0; mf < 4; ++mf)
        #pragma unroll
        for (int hh = 0; hh < 2; ++hh) {
            int m = m0 + wm*64 + mf*16 + hh*8 + (lane >> 2);
            int b = m >> 11, s = m & (SEQ-1);
            #pragma unroll
            for (int nf = 0; nf < 8; ++nf) {
                int n = n0 + wn*64 + nf*8 + (lane & 3)*2;
                int h = n >> 6, d = n & 63;
                float2 lo = lo2f(accl[mf][nf][hh]);
                float v0 = (acc[mf][nf][hh*2+0] + lo.x + bias[n])   * alpha;
                float v1 = (acc[mf][nf][hh*2+1] + lo.y + bias[n+1]) * alpha;
                size_t o = ((size_t)(b*NH + h)*SEQ + s)*HD + d;
                if (dual) {
                    uint32_t hp, lp; split2h(v0, v1, hp, lp);
                    *(uint32_t*)(dh + o) = hp;
                    *(uint32_t*)(dl + o) = lp;
                } else {
                    *(uint32_t*)(dh + o) = packh(v0, v1);
                }
            }
        }
}

// ---------------- output projection ------------------------------------------
__global__ void __launch_bounds__(256) outproj_kernel(
    const float* __restrict__ bo, float* __restrict__ out)
{
    const int m0 = blockIdx.y << 8, n0 = blockIdx.x << 7;
    float acc[4][8][4] = {};
    uint32_t accl[4][8][2] = {};
    gemm_body_256(g_Ahi, g_Alo, g_Wo, m0, n0, acc, accl);

    const int lane = threadIdx.x & 31, wid = threadIdx.x >> 5;
    const int wm = wid & 3, wn = wid >> 2;
    #pragma unroll
    for (int mf = 0; mf < 4; ++mf)
        #pragma unroll
        for (int hh = 0; hh < 2; ++hh) {
            int m = m0 + wm*64 + mf*16 + hh*8 + (lane >> 2);
            #pragma unroll
            for (int nf = 0; nf < 8; ++nf) {
                int n = n0 + wn*64 + nf*8 + (lane & 3)*2;
                float2 lo = lo2f(accl[mf][nf][hh]);
                float2 v = make_float2(acc[mf][nf][hh*2+0] + lo.x + bo[n],
                                       acc[mf][nf][hh*2+1] + lo.y + bo[n+1]);
                *(float2*)&out[(size_t)m * EMB + n] = v;
            }
        }
}

// ---------------- flash attention: BQ=256, 8 warps m32, 3-stage KV ----------
#define ASP     144
#define QL_OFF  36864
#define KV_BASE 73728
#define V_OFF   9216
#define KV_STG  18432
#define ATT_SMEM (KV_BASE + 3*KV_STG)   // 129024

__global__ void __launch_bounds__(256) attn_kernel()
{
    extern __shared__ char sm[];
    const uint32_t smb = smem_u32(sm);
    const int tid = threadIdx.x, lane = tid & 31, w = tid >> 5;
    const int bh = blockIdx.y, q0 = blockIdx.x << 8;

    const __half* Qh = g_Qh + ((size_t)bh*SEQ + q0)*HD;
    const __half* Ql = g_Ql + ((size_t)bh*SEQ + q0)*HD;
    const __half* Kh = g_Kh + (size_t)bh*SEQ*HD;
    const __half* Vh = g_Vh + (size_t)bh*SEQ*HD;

    auto issue_kv = [&](int it) {
        const int kv0 = it << 6;
        const uint32_t sb = smb + KV_BASE + (uint32_t)(it % 3) * KV_STG;
        #pragma unroll
        for (int j = 0; j < 4; ++j) {
            int idx = tid + (j << 8);
            int arr = idx >> 9, c = idx & 511;
            int row = c >> 3, seg = c & 7;
            size_t ga = (size_t)(kv0 + row)*HD + seg*8;
            const __half* g = (arr == 0) ? Kh : Vh;
            cp16(sb + arr*V_OFF + row*ASP + seg*16, g + ga);
        }
        CP_COMMIT();
    };

    #pragma unroll
    for (int j = 0; j < 16; ++j) {
        int idx = tid + (j << 8);
        int lo_ = idx >> 11, c = idx & 2047;
        int row = c >> 3, seg = c & 7;
        const __half* g = (lo_ ? Ql : Qh) + (size_t)row*HD + seg*8;
        cp16(smb + (lo_ ? QL_OFF : 0) + row*ASP + seg*16, g);
    }
    CP_COMMIT();
    issue_kv(0);
    issue_kv(1);

    float o[2][8][4] = {};
    float mrow[2][2], lrow[2][2];
    #pragma unroll
    for (int a = 0; a < 2; ++a)
        for (int c = 0; c < 2; ++c) { mrow[a][c] = __int_as_float(0xff800000); lrow[a][c] = 0.f; }

    for (int it = 0; it < SEQ/64; ++it) {
        if (it + 1 < SEQ/64) CP_WAIT(1); else CP_WAIT(0);
        __syncthreads();
        if (it + 2 < SEQ/64) issue_kv(it + 2);
        const uint32_t kb = smb + KV_BASE + (uint32_t)(it % 3) * KV_STG;

        // S = Q K^T
        float s[2][8][4] = {};
        #pragma unroll
        for (int ks = 0; ks < 4; ++ks) {
            uint32_t aQh[2][4], aQl[2][4], bF[4][4];
            uint32_t qcol = ks*32 + ((lane>>4)&1)*16;
            #pragma unroll
            for (int mf = 0; mf < 2; ++mf) {
                uint32_t qrow = w*32 + mf*16 + ((lane>>3)&1)*8 + (lane&7);
                ldsm4(aQh[mf], smb + qrow*ASP + qcol);
                ldsm4(aQl[mf], smb + QL_OFF + qrow*ASP + qcol);
            }
            #pragma unroll
            for (int ng = 0; ng < 4; ++ng) {
                uint32_t krow = ng*16 + ((lane>>4)&1)*8 + (lane&7);
                uint32_t kcol = ks*32 + ((lane>>3)&1)*16;
                ldsm4(bF[ng], kb + krow*ASP + kcol);
            }
            #pragma unroll
            for (int ng = 0; ng < 4; ++ng)
                #pragma unroll
                for (int mf = 0; mf < 2; ++mf) {
                    mma_h(s[mf][2*ng],   aQh[mf], bF[ng][0], bF[ng][1]);
                    mma_h(s[mf][2*ng+1], aQh[mf], bF[ng][2], bF[ng][3]);
                }
            #pragma unroll
            for (int ng = 0; ng < 4; ++ng)
                #pragma unroll
                for (int mf = 0; mf < 2; ++mf) {
                    mma_h(s[mf][2*ng],   aQl[mf], bF[ng][0], bF[ng][1]);
                    mma_h(s[mf][2*ng+1], aQl[mf], bF[ng][2], bF[ng][3]);
                }
        }

        // online softmax bookkeeping (max + correction); sums come from ones-MMA
        float csave[2][2], mnv[2][2];
        #pragma unroll
        for (int mf = 0; mf < 2; ++mf) {
            float mx0 = fmaxf(s[mf][0][0], s[mf][0][1]), mx1 = fmaxf(s[mf][0][2], s[mf][0][3]);
            #pragma unroll
            for (int j = 1; j < 8; ++j) {
                mx0 = fmaxf(mx0, fmaxf(s[mf][j][0], s[mf][j][1]));
                mx1 = fmaxf(mx1, fmaxf(s[mf][j][2], s[mf][j][3]));
            }
            mx0 = fmaxf(mx0, __shfl_xor_sync(0xffffffffu, mx0, 1));
            mx0 = fmaxf(mx0, __shfl_xor_sync(0xffffffffu, mx0, 2));
            mx1 = fmaxf(mx1, __shfl_xor_sync(0xffffffffu, mx1, 1));
            mx1 = fmaxf(mx1, __shfl_xor_sync(0xffffffffu, mx1, 2));
            float mn0 = fmaxf(mrow[mf][0], mx0), mn1 = fmaxf(mrow[mf][1], mx1);
            float c0 = exp2f(mrow[mf][0] - mn0), c1 = exp2f(mrow[mf][1] - mn1);
            mrow[mf][0] = mn0; mrow[mf][1] = mn1;
            mnv[mf][0] = mn0; mnv[mf][1] = mn1;
            csave[mf][0] = c0; csave[mf][1] = c1;
            #pragma unroll
            for (int j = 0; j < 8; ++j) {
                o[mf][j][0] *= c0; o[mf][j][1] *= c0; o[mf][j][2] *= c1; o[mf][j][3] *= c1;
            }
        }

        // O += P V ; l += P @ ones.  P = ex2(s - mn) in fp16x2 directly.
        float lacc[2][4] = {};
        #pragma unroll
        for (int ks = 0; ks < 4; ++ks) {
            uint32_t aP[2][4];
            #pragma unroll
            for (int mf = 0; mf < 2; ++mf) {
                float mn0 = mnv[mf][0], mn1 = mnv[mf][1];
                aP[mf][0] = ex2h2(packh(s[mf][2*ks][0]   - mn0, s[mf][2*ks][1]   - mn0));
                aP[mf][1] = ex2h2(packh(s[mf][2*ks][2]   - mn1, s[mf][2*ks][3]   - mn1));
                aP[mf][2] = ex2h2(packh(s[mf][2*ks+1][0] - mn0, s[mf][2*ks+1][1] - mn0));
                aP[mf][3] = ex2h2(packh(s[mf][2*ks+1][2] - mn1, s[mf][2*ks+1][3] - mn1));
                mma_h(lacc[mf], aP[mf], ONESH2, ONESH2);
            }
            #pragma unroll
            for (int ng = 0; ng < 4; ++ng) {
                uint32_t bH[4];
                uint32_t vrow = ks*16 + ((lane>>3)&1)*8 + (lane&7);
                uint32_t vcol = ng*32 + ((lane>>4)&1)*16;
                ldsm4t(bH, kb + V_OFF + vrow*ASP + vcol);
                #pragma unroll
                for (int mf = 0; mf < 2; ++mf) {
                    mma_h(o[mf][2*ng],   aP[mf], bH[0], bH[1]);
                    mma_h(o[mf][2*ng+1], aP[mf], bH[2], bH[3]);
                }
            }
        }
        #pragma unroll
        for (int mf = 0; mf < 2; ++mf) {
            lrow[mf][0] = lrow[mf][0] * csave[mf][0] + lacc[mf][0];
            lrow[mf][1] = lrow[mf][1] * csave[mf][1] + lacc[mf][2];
        }
    }

    // epilogue -> fp16 hi/lo in [B*S][EMB]
    const int b = bh >> 4, h = bh & 15;
    #pragma unroll
    for (int mf = 0; mf < 2; ++mf) {
        float inv0 = 1.0f / lrow[mf][0], inv1 = 1.0f / lrow[mf][1];
        const int r0 = q0 + w*32 + mf*16 + (lane >> 2), r1 = r0 + 8;
        #pragma unroll
        for (int nf = 0; nf < 8; ++nf) {
            int d = nf*8 + (lane & 3)*2;
            int e = h*HD + d;
            uint32_t hp, lp;
            split2h(o[mf][nf][0]*inv0, o[mf][nf][1]*inv0, hp, lp);
            size_t o0 = ((size_t)(b*SEQ + r0))*EMB + e;
            *(uint32_t*)(g_Ahi + o0) = hp;
            *(uint32_t*)(g_Alo + o0) = lp;
            split2h(o[mf][nf][2]*inv1, o[mf][nf][3]*inv1, hp, lp);
            size_t o1 = ((size_t)(b*SEQ + r1))*EMB + e;
            *(uint32_t*)(g_Ahi + o1) = hp;
            *(uint32_t*)(g_Alo + o1) = lp;
        }
    }
}

// ---------------------------------------------------------------------------
extern "C" void kernel_launch(void* const* d_in, const int* in_sizes, int n_in,
                              void* d_out, int out_size)
{
    (void)in_sizes; (void)n_in; (void)out_size;
    const float* x  = (const float*)d_in[0];
    const float* Wq = (const float*)d_in[1];
    const float* bq = (const float*)d_in[2];
    const float* Wk = (const float*)d_in[3];
    const float* bk = (const float*)d_in[4];
    const float* Wv = (const float*)d_in[5];
    const float* bv = (const float*)d_in[6];
    const float* Wo = (const float*)d_in[7];
    const float* bo = (const float*)d_in[8];
    float* out = (float*)d_out;

    cudaFuncSetAttribute(qkv_kernel,     cudaFuncAttributeMaxDynamicSharedMemorySize, GEMM_SMEM);
    cudaFuncSetAttribute(outproj_kernel, cudaFuncAttributeMaxDynamicSharedMemorySize, GEMM_SMEM);
    cudaFuncSetAttribute(attn_kernel,    cudaFuncAttributeMaxDynamicSharedMemorySize, ATT_SMEM);

    split_all_kernel<<<4096, 256>>>(x, Wq, Wk, Wv, Wo);

    dim3 gqkv(EMB/128, MTOK/256, 3);     // 8 x 16 x 3
    qkv_kernel<<<gqkv, 256, GEMM_SMEM>>>(bq, bk, bv);

    dim3 gattn(SEQ/256, BHN);            // 8 x 32
    attn_kernel<<<gattn, 256, ATT_SMEM>>>();

    dim3 gout(EMB/128, MTOK/256);        // 8 x 16
    outproj_kernel<<<gout, 256, GEMM_SMEM>>>(bo, out);
}

// round 11
// speedup vs baseline: 1.2208x; 1.2208x over previous
#include <cuda_runtime.h>
#include <cuda_fp16.h>
#include <cstdint>

#define EMB   1024
#define NH    16
#define HD    64
#define BATCH 2
#define SEQ   2048
#define MTOK  (BATCH*SEQ)   // 4096
#define BHN   (BATCH*NH)    // 32

// ---------------- scratch (__device__ globals; no allocs allowed) -----------
__device__ __half g_Xhi[(size_t)MTOK*EMB], g_Xlo[(size_t)MTOK*EMB];
__device__ __half g_A[(size_t)MTOK*EMB];
__device__ __half g_Qh[(size_t)MTOK*EMB], g_Ql[(size_t)MTOK*EMB];
__device__ __half g_Kh[(size_t)MTOK*EMB];
__device__ __half g_Vh[(size_t)MTOK*EMB];
__device__ __half g_Wq[(size_t)EMB*EMB], g_Wk[(size_t)EMB*EMB];
__device__ __half g_Wv[(size_t)EMB*EMB], g_Wo[(size_t)EMB*EMB];

// ---------------- helpers ---------------------------------------------------
__device__ __forceinline__ uint32_t smem_u32(const void* p) {
    uint32_t a;
    asm("{ .reg .u64 t; cvta.to.shared.u64 t, %1; cvt.u32.u64 %0, t; }" : "=r"(a) : "l"(p));
    return a;
}
__device__ __forceinline__ void cp16(uint32_t d, const void* s) {
    asm volatile("cp.async.cg.shared.global [%0], [%1], 16;" :: "r"(d), "l"(s));
}
#define CP_COMMIT() asm volatile("cp.async.commit_group;")
#define CP_WAIT(n)  asm volatile("cp.async.wait_group %0;" :: "n"(n))

__device__ __forceinline__ void ldsm4(uint32_t (&r)[4], uint32_t a) {
    asm volatile("ldmatrix.sync.aligned.m8n8.x4.shared.b16 {%0,%1,%2,%3}, [%4];"
        : "=r"(r[0]), "=r"(r[1]), "=r"(r[2]), "=r"(r[3]) : "r"(a));
}
__device__ __forceinline__ void ldsm4t(uint32_t (&r)[4], uint32_t a) {
    asm volatile("ldmatrix.sync.aligned.m8n8.x4.trans.shared.b16 {%0,%1,%2,%3}, [%4];"
        : "=r"(r[0]), "=r"(r[1]), "=r"(r[2]), "=r"(r[3]) : "r"(a));
}
__device__ __forceinline__ void mma_h(float (&c)[4], const uint32_t (&a)[4], uint32_t b0, uint32_t b1) {
    asm("mma.sync.aligned.m16n8k16.row.col.f32.f16.f16.f32 "
        "{%0,%1,%2,%3}, {%4,%5,%6,%7}, {%8,%9}, {%0,%1,%2,%3};"
        : "+f"(c[0]), "+f"(c[1]), "+f"(c[2]), "+f"(c[3])
        : "r"(a[0]), "r"(a[1]), "r"(a[2]), "r"(a[3]), "r"(b0), "r"(b1));
}
__device__ __forceinline__ uint32_t packh(float v0, float v1) {
    __half2 h = __floats2half2_rn(v0, v1);
    return *(uint32_t*)&h;
}
__device__ __forceinline__ void split2h(float v0, float v1, uint32_t &hp, uint32_t &lp) {
    __half2 h = __floats2half2_rn(v0, v1);
    hp = *(uint32_t*)&h;
    float h0 = __half2float(__low2half(h));
    float h1 = __half2float(__high2half(h));
    lp = packh(v0 - h0, v1 - h1);
}
__device__ __forceinline__ uint32_t ex2h2(uint32_t x) {
    uint32_t r;
    asm("ex2.approx.f16x2 %0, %1;" : "=r"(r) : "r"(x));
    return r;
}
#define ONESH2 0x3C003C00u   // half2(1.0, 1.0)

// ---------------- fused fp32 -> fp16 split (X hi/lo; W hi only) --------------
__global__ __launch_bounds__(256) void split_all_kernel(
    const float* __restrict__ x,  const float* __restrict__ wq,
    const float* __restrict__ wk, const float* __restrict__ wv,
    const float* __restrict__ wo)
{
    int i = blockIdx.x * 256 + threadIdx.x;
    if (i < 524288) {
        float4 a = ((const float4*)x)[2*i];
        float4 b = ((const float4*)x)[2*i + 1];
        float v[8] = {a.x, a.y, a.z, a.w, b.x, b.y, b.z, b.w};
        uint32_t hp[4], lp[4];
        #pragma unroll
        for (int j = 0; j < 4; j++) split2h(v[2*j], v[2*j+1], hp[j], lp[j]);
        ((uint4*)g_Xhi)[i] = make_uint4(hp[0], hp[1], hp[2], hp[3]);
        ((uint4*)g_Xlo)[i] = make_uint4(lp[0], lp[1], lp[2], lp[3]);
    } else {
        int j = i - 524288;
        int w = j >> 17;
        int off = j & 131071;
        const float* src; __half* hi;
        if (w == 0)      { src = wq; hi = g_Wq; }
        else if (w == 1) { src = wk; hi = g_Wk; }
        else if (w == 2) { src = wv; hi = g_Wv; }
        else             { src = wo; hi = g_Wo; }
        float4 a = ((const float4*)src)[2*off];
        float4 b = ((const float4*)src)[2*off + 1];
        uint32_t hp[4];
        hp[0] = packh(a.x, a.y); hp[1] = packh(a.z, a.w);
        hp[2] = packh(b.x, b.y); hp[3] = packh(b.z, b.w);
        ((uint4*)hi)[off] = make_uint4(hp[0], hp[1], hp[2], hp[3]);
    }
}

// ---------------- GEMM body: 256x128 tile, 256 thr, warp 64x64 --------------
// USE_LO: A is 2-term (hi+lo); otherwise single-term (half the MMAs + loads).
#define SPAD   80
#define AL_OFF 20480
#define BH_OFF 40960
#define STG    51200
#define GEMM_SMEM (3*STG)   // 153600
#define NITER (EMB/32)      // 32

template <bool USE_LO>
__device__ __forceinline__ void gemm_body_256(
    const __half* __restrict__ Ah, const __half* __restrict__ Al,
    const __half* __restrict__ Wh,
    int m0, int n0, float (&acc)[4][8][4])
{
    extern __shared__ char sm[];
    const uint32_t smb = smem_u32(sm);
    const int tid = threadIdx.x, lane = tid & 31, wid = tid >> 5;
    const int wm = wid & 3, wn = wid >> 2;

    auto issue = [&](int it) {
        const int k0 = it << 5;
        const uint32_t sb = smb + (uint32_t)(it % 3) * STG;
        #pragma unroll
        for (int j = 0; j < 10; ++j) {
            int idx = tid + (j << 8);
            if (idx < 1024) {
                int row = idx >> 2, seg = idx & 3;
                cp16(sb + row*SPAD + seg*16, Ah + (size_t)(m0 + row)*EMB + k0 + seg*8);
            } else if (idx < 2048) {
                if (USE_LO) {
                    int c = idx - 1024, row = c >> 2, seg = c & 3;
                    cp16(sb + AL_OFF + row*SPAD + seg*16, Al + (size_t)(m0 + row)*EMB + k0 + seg*8);
                }
            } else {
                int c = idx - 2048, row = c >> 2, seg = c & 3;
                cp16(sb + BH_OFF + row*SPAD + seg*16, Wh + (size_t)(n0 + row)*EMB + k0 + seg*8);
            }
        }
        CP_COMMIT();
    };

    issue(0); issue(1);
    for (int it = 0; it < NITER; ++it) {
        if (it + 1 < NITER) CP_WAIT(1); else CP_WAIT(0);
        __syncthreads();
        if (it + 2 < NITER) issue(it + 2);
        const uint32_t sb = smb + (uint32_t)(it % 3) * STG;
        #pragma unroll
        for (int ks = 0; ks < 2; ++ks) {
            uint32_t aH[4][4], aL[4][4], bF[4][4];
            uint32_t acol = ks*32 + ((lane>>4)&1)*16;
            #pragma unroll
            for (int mf = 0; mf < 4; ++mf) {
                uint32_t row = wm*64 + mf*16 + ((lane>>3)&1)*8 + (lane&7);
                ldsm4(aH[mf], sb + row*SPAD + acol);
                if (USE_LO) ldsm4(aL[mf], sb + AL_OFF + row*SPAD + acol);
            }
            #pragma unroll
            for (int ng = 0; ng < 4; ++ng) {
                uint32_t row = wn*64 + ng*16 + ((lane>>4)&1)*8 + (lane&7);
                uint32_t col = ks*32 + ((lane>>3)&1)*16;
                ldsm4(bF[ng], sb + BH_OFF + row*SPAD + col);
            }
            #pragma unroll
            for (int ng = 0; ng < 4; ++ng)
                #pragma unroll
                for (int mf = 0; mf < 4; ++mf) {
                    mma_h(acc[mf][2*ng],   aH[mf], bF[ng][0], bF[ng][1]);
                    mma_h(acc[mf][2*ng+1], aH[mf], bF[ng][2], bF[ng][3]);
                }
            if (USE_LO) {
                #pragma unroll
                for (int ng = 0; ng < 4; ++ng)
                    #pragma unroll
                    for (int mf = 0; mf < 4; ++mf) {
                        mma_h(acc[mf][2*ng],   aL[mf], bF[ng][0], bF[ng][1]);
                        mma_h(acc[mf][2*ng+1], aL[mf], bF[ng][2], bF[ng][3]);
                    }
            }
        }
    }
}

// ---------------- QKV projection ---------------------------------------------
// Q: 2-term X (scores are precision-critical), stored hi+lo.
// K,V: single-term X (stored fp16 anyway), half the MMAs.
__global__ void __launch_bounds__(256) qkv_kernel(
    const float* __restrict__ bq, const float* __restrict__ bk, const float* __restrict__ bv)
{
    const __half* Wh; const float* bias;
    __half *dh, *dl; float alpha; int dual;
    if (blockIdx.z == 0)      { Wh = g_Wq; bias = bq; dh = g_Qh; dl = g_Ql; alpha = 0.18033688011112042f; dual = 1; }
    else if (blockIdx.z == 1) { Wh = g_Wk; bias = bk; dh = g_Kh; dl = 0;    alpha = 1.0f; dual = 0; }
    else                      { Wh = g_Wv; bias = bv; dh = g_Vh; dl = 0;    alpha = 1.0f; dual = 0; }

    const int m0 = blockIdx.y << 8, n0 = blockIdx.x << 7;
    float acc[4][8][4] = {};
    if (dual) gemm_body_256<true >(g_Xhi, g_Xlo, Wh, m0, n0, acc);
    else      gemm_body_256<false>(g_Xhi, g_Xlo, Wh, m0, n0, acc);

    const int lane = threadIdx.x & 31, wid = threadIdx.x >> 5;
    const int wm = wid & 3, wn = wid >> 2;
    #pragma unroll
    for (int mf = 0; mf < 4; ++mf)
        #pragma unroll
        for (int hh = 0; hh < 2; ++hh) {
            int m = m0 + wm*64 + mf*16 + hh*8 + (lane >> 2);
            int b = m >> 11, s = m & (SEQ-1);
            #pragma unroll
            for (int nf = 0; nf < 8; ++nf) {
                int n = n0 + wn*64 + nf*8 + (lane & 3)*2;
                int h = n >> 6, d = n & 63;
                float v0 = (acc[mf][nf][hh*2+0] + bias[n])   * alpha;
                float v1 = (acc[mf][nf][hh*2+1] + bias[n+1]) * alpha;
                size_t o = ((size_t)(b*NH + h)*SEQ + s)*HD + d;
                if (dual) {
                    uint32_t hp, lp; split2h(v0, v1, hp, lp);
                    *(uint32_t*)(dh + o) = hp;
                    *(uint32_t*)(dl + o) = lp;
                } else {
                    *(uint32_t*)(dh + o) = packh(v0, v1);
                }
            }
        }
}

// ---------------- output projection (A single-term) --------------------------
__global__ void __launch_bounds__(256) outproj_kernel(
    const float* __restrict__ bo, float* __restrict__ out)
{
    const int m0 = blockIdx.y << 8, n0 = blockIdx.x << 7;
    float acc[4][8][4] = {};
    gemm_body_256<false>(g_A, g_A, g_Wo, m0, n0, acc);

    const int lane = threadIdx.x & 31, wid = threadIdx.x >> 5;
    const int wm = wid & 3, wn = wid >> 2;
    #pragma unroll
    for (int mf = 0; mf < 4; ++mf)
        #pragma unroll
        for (int hh = 0; hh < 2; ++hh) {
            int m = m0 + wm*64 + mf*16 + hh*8 + (lane >> 2);
            #pragma unroll
            for (int nf = 0; nf < 8; ++nf) {
                int n = n0 + wn*64 + nf*8 + (lane & 3)*2;
                float2 v = make_float2(acc[mf][nf][hh*2+0] + bo[n],
                                       acc[mf][nf][hh*2+1] + bo[n+1]);
                *(float2*)&out[(size_t)m * EMB + n] = v;
            }
        }
}

// ---------------- flash attention: BQ=256, 8 warps m32, 3-stage KV ----------
#define ASP     144
#define QL_OFF  36864
#define KV_BASE 73728
#define V_OFF   9216
#define KV_STG  18432
#define ATT_SMEM (KV_BASE + 3*KV_STG)   // 129024

__global__ void __launch_bounds__(256) attn_kernel()
{
    extern __shared__ char sm[];
    const uint32_t smb = smem_u32(sm);
    const int tid = threadIdx.x, lane = tid & 31, w = tid >> 5;
    const int bh = blockIdx.y, q0 = blockIdx.x << 8;

    const __half* Qh = g_Qh + ((size_t)bh*SEQ + q0)*HD;
    const __half* Ql = g_Ql + ((size_t)bh*SEQ + q0)*HD;
    const __half* Kh = g_Kh + (size_t)bh*SEQ*HD;
    const __half* Vh = g_Vh + (size_t)bh*SEQ*HD;

    auto issue_kv = [&](int it) {
        const int kv0 = it << 6;
        const uint32_t sb = smb + KV_BASE + (uint32_t)(it % 3) * KV_STG;
        #pragma unroll
        for (int j = 0; j < 4; ++j) {
            int idx = tid + (j << 8);
            int arr = idx >> 9, c = idx & 511;
            int row = c >> 3, seg = c & 7;
            size_t ga = (size_t)(kv0 + row)*HD + seg*8;
            const __half* g = (arr == 0) ? Kh : Vh;
            cp16(sb + arr*V_OFF + row*ASP + seg*16, g + ga);
        }
        CP_COMMIT();
    };

    #pragma unroll
    for (int j = 0; j < 16; ++j) {
        int idx = tid + (j << 8);
        int lo_ = idx >> 11, c = idx & 2047;
        int row = c >> 3, seg = c & 7;
        const __half* g = (lo_ ? Ql : Qh) + (size_t)row*HD + seg*8;
        cp16(smb + (lo_ ? QL_OFF : 0) + row*ASP + seg*16, g);
    }
    CP_COMMIT();
    issue_kv(0);
    issue_kv(1);

    float o[2][8][4] = {};
    float mrow[2][2], lrow[2][2];
    #pragma unroll
    for (int a = 0; a < 2; ++a)
        for (int c = 0; c < 2; ++c) { mrow[a][c] = __int_as_float(0xff800000); lrow[a][c] = 0.f; }

    for (int it = 0; it < SEQ/64; ++it) {
        if (it + 1 < SEQ/64) CP_WAIT(1); else CP_WAIT(0);
        __syncthreads();
        if (it + 2 < SEQ/64) issue_kv(it + 2);
        const uint32_t kb = smb + KV_BASE + (uint32_t)(it % 3) * KV_STG;

        // S = Q K^T
        float s[2][8][4] = {};
        #pragma unroll
        for (int ks = 0; ks < 4; ++ks) {
            uint32_t aQh[2][4], aQl[2][4], bF[4][4];
            uint32_t qcol = ks*32 + ((lane>>4)&1)*16;
            #pragma unroll
            for (int mf = 0; mf < 2; ++mf) {
                uint32_t qrow = w*32 + mf*16 + ((lane>>3)&1)*8 + (lane&7);
                ldsm4(aQh[mf], smb + qrow*ASP + qcol);
                ldsm4(aQl[mf], smb + QL_OFF + qrow*ASP + qcol);
            }
            #pragma unroll
            for (int ng = 0; ng < 4; ++ng) {
                uint32_t krow = ng*16 + ((lane>>4)&1)*8 + (lane&7);
                uint32_t kcol = ks*32 + ((lane>>3)&1)*16;
                ldsm4(bF[ng], kb + krow*ASP + kcol);
            }
            #pragma unroll
            for (int ng = 0; ng < 4; ++ng)
                #pragma unroll
                for (int mf = 0; mf < 2; ++mf) {
                    mma_h(s[mf][2*ng],   aQh[mf], bF[ng][0], bF[ng][1]);
                    mma_h(s[mf][2*ng+1], aQh[mf], bF[ng][2], bF[ng][3]);
                }
            #pragma unroll
            for (int ng = 0; ng < 4; ++ng)
                #pragma unroll
                for (int mf = 0; mf < 2; ++mf) {
                    mma_h(s[mf][2*ng],   aQl[mf], bF[ng][0], bF[ng][1]);
                    mma_h(s[mf][2*ng+1], aQl[mf], bF[ng][2], bF[ng][3]);
                }
        }

        // online softmax bookkeeping (max + correction); sums via ones-MMA
        float csave[2][2], mnv[2][2];
        #pragma unroll
        for (int mf = 0; mf < 2; ++mf) {
            float mx0 = fmaxf(s[mf][0][0], s[mf][0][1]), mx1 = fmaxf(s[mf][0][2], s[mf][0][3]);
            #pragma unroll
            for (int j = 1; j < 8; ++j) {
                mx0 = fmaxf(mx0, fmaxf(s[mf][j][0], s[mf][j][1]));
                mx1 = fmaxf(mx1, fmaxf(s[mf][j][2], s[mf][j][3]));
            }
            mx0 = fmaxf(mx0, __shfl_xor_sync(0xffffffffu, mx0, 1));
            mx0 = fmaxf(mx0, __shfl_xor_sync(0xffffffffu, mx0, 2));
            mx1 = fmaxf(mx1, __shfl_xor_sync(0xffffffffu, mx1, 1));
            mx1 = fmaxf(mx1, __shfl_xor_sync(0xffffffffu, mx1, 2));
            float mn0 = fmaxf(mrow[mf][0], mx0), mn1 = fmaxf(mrow[mf][1], mx1);
            float c0 = exp2f(mrow[mf][0] - mn0), c1 = exp2f(mrow[mf][1] - mn1);
            mrow[mf][0] = mn0; mrow[mf][1] = mn1;
            mnv[mf][0] = mn0; mnv[mf][1] = mn1;
            csave[mf][0] = c0; csave[mf][1] = c1;
            #pragma unroll
            for (int j = 0; j < 8; ++j) {
                o[mf][j][0] *= c0; o[mf][j][1] *= c0; o[mf][j][2] *= c1; o[mf][j][3] *= c1;
            }
        }

        // O += P V ; l += P @ ones.  P = ex2(s - mn) in fp16x2 directly.
        float lacc[2][4] = {};
        #pragma unroll
        for (int ks = 0; ks < 4; ++ks) {
            uint32_t aP[2][4];
            #pragma unroll
            for (int mf = 0; mf < 2; ++mf) {
                float mn0 = mnv[mf][0], mn1 = mnv[mf][1];
                aP[mf][0] = ex2h2(packh(s[mf][2*ks][0]   - mn0, s[mf][2*ks][1]   - mn0));
                aP[mf][1] = ex2h2(packh(s[mf][2*ks][2]   - mn1, s[mf][2*ks][3]   - mn1));
                aP[mf][2] = ex2h2(packh(s[mf][2*ks+1][0] - mn0, s[mf][2*ks+1][1] - mn0));
                aP[mf][3] = ex2h2(packh(s[mf][2*ks+1][2] - mn1, s[mf][2*ks+1][3] - mn1));
                mma_h(lacc[mf], aP[mf], ONESH2, ONESH2);
            }
            #pragma unroll
            for (int ng = 0; ng < 4; ++ng) {
                uint32_t bH[4];
                uint32_t vrow = ks*16 + ((lane>>3)&1)*8 + (lane&7);
                uint32_t vcol = ng*32 + ((lane>>4)&1)*16;
                ldsm4t(bH, kb + V_OFF + vrow*ASP + vcol);
                #pragma unroll
                for (int mf = 0; mf < 2; ++mf) {
                    mma_h(o[mf][2*ng],   aP[mf], bH[0], bH[1]);
                    mma_h(o[mf][2*ng+1], aP[mf], bH[2], bH[3]);
                }
            }
        }
        #pragma unroll
        for (int mf = 0; mf < 2; ++mf) {
            lrow[mf][0] = lrow[mf][0] * csave[mf][0] + lacc[mf][0];
            lrow[mf][1] = lrow[mf][1] * csave[mf][1] + lacc[mf][2];
        }
    }

    // epilogue -> single fp16 A in [B*S][EMB]
    const int b = bh >> 4, h = bh & 15;
    #pragma unroll
    for (int mf = 0; mf < 2; ++mf) {
        float inv0 = 1.0f / lrow[mf][0], inv1 = 1.0f / lrow[mf][1];
        const int r0 = q0 + w*32 + mf*16 + (lane >> 2), r1 = r0 + 8;
        #pragma unroll
        for (int nf = 0; nf < 8; ++nf) {
            int d = nf*8 + (lane & 3)*2;
            int e = h*HD + d;
            *(uint32_t*)(g_A + ((size_t)(b*SEQ + r0))*EMB + e) =
                packh(o[mf][nf][0]*inv0, o[mf][nf][1]*inv0);
            *(uint32_t*)(g_A + ((size_t)(b*SEQ + r1))*EMB + e) =
                packh(o[mf][nf][2]*inv1, o[mf][nf][3]*inv1);
        }
    }
}

// ---------------------------------------------------------------------------
extern "C" void kernel_launch(void* const* d_in, const int* in_sizes, int n_in,
                              void* d_out, int out_size)
{
    (void)in_sizes; (void)n_in; (void)out_size;
    const float* x  = (const float*)d_in[0];
    const float* Wq = (const float*)d_in[1];
    const float* bq = (const float*)d_in[2];
    const float* Wk = (const float*)d_in[3];
    const float* bk = (const float*)d_in[4];
    const float* Wv = (const float*)d_in[5];
    const float* bv = (const float*)d_in[6];
    const float* Wo = (const float*)d_in[7];
    const float* bo = (const float*)d_in[8];
    float* out = (float*)d_out;

    cudaFuncSetAttribute(qkv_kernel,     cudaFuncAttributeMaxDynamicSharedMemorySize, GEMM_SMEM);
    cudaFuncSetAttribute(outproj_kernel, cudaFuncAttributeMaxDynamicSharedMemorySize, GEMM_SMEM);
    cudaFuncSetAttribute(attn_kernel,    cudaFuncAttributeMaxDynamicSharedMemorySize, ATT_SMEM);

    split_all_kernel<<<4096, 256>>>(x, Wq, Wk, Wv, Wo);

    dim3 gqkv(EMB/128, MTOK/256, 3);     // 8 x 16 x 3
    qkv_kernel<<<gqkv, 256, GEMM_SMEM>>>(bq, bk, bv);

    dim3 gattn(SEQ/256, BHN);            // 8 x 32
    attn_kernel<<<gattn, 256, ATT_SMEM>>>();

    dim3 gout(EMB/128, MTOK/256);        // 8 x 16
    outproj_kernel<<<gout, 256, GEMM_SMEM>>>(bo, out);
}

// round 12
// speedup vs baseline: 1.3883x; 1.1373x over previous
#include <cuda_runtime.h>
#include <cuda_fp16.h>
#include <cstdint>

#define EMB   1024
#define NH    16
#define HD    64
#define BATCH 2
#define SEQ   2048
#define MTOK  (BATCH*SEQ)   // 4096
#define BHN   (BATCH*NH)    // 32

// ---------------- scratch (__device__ globals; no allocs allowed) -----------
__device__ __half g_Xhi[(size_t)MTOK*EMB], g_Xlo[(size_t)MTOK*EMB];
__device__ __half g_A[(size_t)MTOK*EMB];
__device__ __half g_Qh[(size_t)MTOK*EMB], g_Ql[(size_t)MTOK*EMB];
__device__ __half g_Kh[(size_t)MTOK*EMB];
__device__ __half g_Vh[(size_t)MTOK*EMB];
__device__ __half g_Wq[(size_t)EMB*EMB], g_Wk[(size_t)EMB*EMB];
__device__ __half g_Wv[(size_t)EMB*EMB], g_Wo[(size_t)EMB*EMB];

// ---------------- helpers ---------------------------------------------------
__device__ __forceinline__ uint32_t smem_u32(const void* p) {
    uint32_t a;
    asm("{ .reg .u64 t; cvta.to.shared.u64 t, %1; cvt.u32.u64 %0, t; }" : "=r"(a) : "l"(p));
    return a;
}
__device__ __forceinline__ void cp16(uint32_t d, const void* s) {
    asm volatile("cp.async.cg.shared.global [%0], [%1], 16;" :: "r"(d), "l"(s));
}
#define CP_COMMIT() asm volatile("cp.async.commit_group;")
#define CP_WAIT(n)  asm volatile("cp.async.wait_group %0;" :: "n"(n))

__device__ __forceinline__ void ldsm4(uint32_t (&r)[4], uint32_t a) {
    asm volatile("ldmatrix.sync.aligned.m8n8.x4.shared.b16 {%0,%1,%2,%3}, [%4];"
        : "=r"(r[0]), "=r"(r[1]), "=r"(r[2]), "=r"(r[3]) : "r"(a));
}
__device__ __forceinline__ void ldsm4t(uint32_t (&r)[4], uint32_t a) {
    asm volatile("ldmatrix.sync.aligned.m8n8.x4.trans.shared.b16 {%0,%1,%2,%3}, [%4];"
        : "=r"(r[0]), "=r"(r[1]), "=r"(r[2]), "=r"(r[3]) : "r"(a));
}
__device__ __forceinline__ void mma_h(float (&c)[4], const uint32_t (&a)[4], uint32_t b0, uint32_t b1) {
    asm("mma.sync.aligned.m16n8k16.row.col.f32.f16.f16.f32 "
        "{%0,%1,%2,%3}, {%4,%5,%6,%7}, {%8,%9}, {%0,%1,%2,%3};"
        : "+f"(c[0]), "+f"(c[1]), "+f"(c[2]), "+f"(c[3])
        : "r"(a[0]), "r"(a[1]), "r"(a[2]), "r"(a[3]), "r"(b0), "r"(b1));
}
__device__ __forceinline__ uint32_t packh(float v0, float v1) {
    __half2 h = __floats2half2_rn(v0, v1);
    return *(uint32_t*)&h;
}
__device__ __forceinline__ void split2h(float v0, float v1, uint32_t &hp, uint32_t &lp) {
    __half2 h = __floats2half2_rn(v0, v1);
    hp = *(uint32_t*)&h;
    float h0 = __half2float(__low2half(h));
    float h1 = __half2float(__high2half(h));
    lp = packh(v0 - h0, v1 - h1);
}
__device__ __forceinline__ uint32_t ex2h2(uint32_t x) {
    uint32_t r;
    asm("ex2.approx.f16x2 %0, %1;" : "=r"(r) : "r"(x));
    return r;
}
#define ONESH2 0x3C003C00u   // half2(1.0, 1.0)

// ---------------- fused fp32 -> fp16 split (X hi/lo; W hi only) --------------
__global__ __launch_bounds__(256) void split_all_kernel(
    const float* __restrict__ x,  const float* __restrict__ wq,
    const float* __restrict__ wk, const float* __restrict__ wv,
    const float* __restrict__ wo)
{
    int i = blockIdx.x * 256 + threadIdx.x;
    if (i < 524288) {
        float4 a = ((const float4*)x)[2*i];
        float4 b = ((const float4*)x)[2*i + 1];
        float v[8] = {a.x, a.y, a.z, a.w, b.x, b.y, b.z, b.w};
        uint32_t hp[4], lp[4];
        #pragma unroll
        for (int j = 0; j < 4; j++) split2h(v[2*j], v[2*j+1], hp[j], lp[j]);
        ((uint4*)g_Xhi)[i] = make_uint4(hp[0], hp[1], hp[2], hp[3]);
        ((uint4*)g_Xlo)[i] = make_uint4(lp[0], lp[1], lp[2], lp[3]);
    } else {
        int j = i - 524288;
        int w = j >> 17;
        int off = j & 131071;
        const float* src; __half* hi;
        if (w == 0)      { src = wq; hi = g_Wq; }
        else if (w == 1) { src = wk; hi = g_Wk; }
        else if (w == 2) { src = wv; hi = g_Wv; }
        else             { src = wo; hi = g_Wo; }
        float4 a = ((const float4*)src)[2*off];
        float4 b = ((const float4*)src)[2*off + 1];
        uint32_t hp[4];
        hp[0] = packh(a.x, a.y); hp[1] = packh(a.z, a.w);
        hp[2] = packh(b.x, b.y); hp[3] = packh(b.z, b.w);
        ((uint4*)hi)[off] = make_uint4(hp[0], hp[1], hp[2], hp[3]);
    }
}

// ---------------- GEMM body: 128x128 CTA, 8 warps 64x32, 2-stage, 2 CTA/SM --
#define SPAD   80
#define AL_OFF 10240
#define BH_OFF 20480
#define STG    30720
#define GEMM_SMEM (2*STG)   // 61440
#define NITER (EMB/32)      // 32

template <bool USE_LO>
__device__ __forceinline__ void gemm_body_128(
    const __half* __restrict__ Ah, const __half* __restrict__ Al,
    const __half* __restrict__ Wh,
    int m0, int n0, float (&acc)[4][4][4])
{
    extern __shared__ char sm[];
    const uint32_t smb = smem_u32(sm);
    const int tid = threadIdx.x, lane = tid & 31, wid = tid >> 5;
    const int wm = wid & 1, wn = wid >> 1;   // 2 x 4 warp grid, warp tile 64x32

    auto issue = [&](int it) {
        const int k0 = it << 5;
        const uint32_t sb = smb + (uint32_t)(it & 1) * STG;
        // 1536 chunks: Ah 512 | Al 512 | B 512 -> 6 per thread
        #pragma unroll
        for (int j = 0; j < 6; ++j) {
            int idx = tid + (j << 8);
            if (idx < 512) {
                int row = idx >> 2, seg = idx & 3;
                cp16(sb + row*SPAD + seg*16, Ah + (size_t)(m0 + row)*EMB + k0 + seg*8);
            } else if (idx < 1024) {
                if (USE_LO) {
                    int c = idx - 512, row = c >> 2, seg = c & 3;
                    cp16(sb + AL_OFF + row*SPAD + seg*16, Al + (size_t)(m0 + row)*EMB + k0 + seg*8);
                }
            } else {
                int c = idx - 1024, row = c >> 2, seg = c & 3;
                cp16(sb + BH_OFF + row*SPAD + seg*16, Wh + (size_t)(n0 + row)*EMB + k0 + seg*8);
            }
        }
        CP_COMMIT();
    };

    issue(0);
    for (int it = 0; it < NITER; ++it) {
        CP_WAIT(0);
        __syncthreads();
        if (it + 1 < NITER) issue(it + 1);
        const uint32_t sb = smb + (uint32_t)(it & 1) * STG;
        #pragma unroll
        for (int ks = 0; ks < 2; ++ks) {
            uint32_t aH[4][4], aL[4][4], bF[2][4];
            uint32_t acol = ks*32 + ((lane>>4)&1)*16;
            #pragma unroll
            for (int mf = 0; mf < 4; ++mf) {
                uint32_t row = wm*64 + mf*16 + ((lane>>3)&1)*8 + (lane&7);
                ldsm4(aH[mf], sb + row*SPAD + acol);
                if (USE_LO) ldsm4(aL[mf], sb + AL_OFF + row*SPAD + acol);
            }
            #pragma unroll
            for (int ng = 0; ng < 2; ++ng) {
                uint32_t row = wn*32 + ng*16 + ((lane>>4)&1)*8 + (lane&7);
                uint32_t col = ks*32 + ((lane>>3)&1)*16;
                ldsm4(bF[ng], sb + BH_OFF + row*SPAD + col);
            }
            #pragma unroll
            for (int ng = 0; ng < 2; ++ng)
                #pragma unroll
                for (int mf = 0; mf < 4; ++mf) {
                    mma_h(acc[mf][2*ng],   aH[mf], bF[ng][0], bF[ng][1]);
                    mma_h(acc[mf][2*ng+1], aH[mf], bF[ng][2], bF[ng][3]);
                }
            if (USE_LO) {
                #pragma unroll
                for (int ng = 0; ng < 2; ++ng)
                    #pragma unroll
                    for (int mf = 0; mf < 4; ++mf) {
                        mma_h(acc[mf][2*ng],   aL[mf], bF[ng][0], bF[ng][1]);
                        mma_h(acc[mf][2*ng+1], aL[mf], bF[ng][2], bF[ng][3]);
                    }
            }
        }
        __syncthreads();
    }
}

// ---------------- QKV projection ---------------------------------------------
__global__ void __launch_bounds__(256, 2) qkv_kernel(
    const float* __restrict__ bq, const float* __restrict__ bk, const float* __restrict__ bv)
{
    const __half* Wh; const float* bias;
    __half *dh, *dl; float alpha; int dual;
    if (blockIdx.z == 0)      { Wh = g_Wq; bias = bq; dh = g_Qh; dl = g_Ql; alpha = 0.18033688011112042f; dual = 1; }
    else if (blockIdx.z == 1) { Wh = g_Wk; bias = bk; dh = g_Kh; dl = 0;    alpha = 1.0f; dual = 0; }
    else                      { Wh = g_Wv; bias = bv; dh = g_Vh; dl = 0;    alpha = 1.0f; dual = 0; }

    const int m0 = blockIdx.y << 7, n0 = blockIdx.x << 7;
    float acc[4][4][4] = {};
    if (dual) gemm_body_128<true >(g_Xhi, g_Xlo, Wh, m0, n0, acc);
    else      gemm_body_128<false>(g_Xhi, g_Xlo, Wh, m0, n0, acc);

    const int lane = threadIdx.x & 31, wid = threadIdx.x >> 5;
    const int wm = wid & 1, wn = wid >> 1;
    #pragma unroll
    for (int mf = 0; mf < 4; ++mf)
        #pragma unroll
        for (int hh = 0; hh < 2; ++hh) {
            int m = m0 + wm*64 + mf*16 + hh*8 + (lane >> 2);
            int b = m >> 11, s = m & (SEQ-1);
            #pragma unroll
            for (int nf = 0; nf < 4; ++nf) {
                int n = n0 + wn*32 + nf*8 + (lane & 3)*2;
                int h = n >> 6, d = n & 63;
                float v0 = (acc[mf][nf][hh*2+0] + bias[n])   * alpha;
                float v1 = (acc[mf][nf][hh*2+1] + bias[n+1]) * alpha;
                size_t o = ((size_t)(b*NH + h)*SEQ + s)*HD + d;
                if (dual) {
                    uint32_t hp, lp; split2h(v0, v1, hp, lp);
                    *(uint32_t*)(dh + o) = hp;
                    *(uint32_t*)(dl + o) = lp;
                } else {
                    *(uint32_t*)(dh + o) = packh(v0, v1);
                }
            }
        }
}

// ---------------- output projection (A single-term) --------------------------
__global__ void __launch_bounds__(256, 2) outproj_kernel(
    const float* __restrict__ bo, float* __restrict__ out)
{
    const int m0 = blockIdx.y << 7, n0 = blockIdx.x << 7;
    float acc[4][4][4] = {};
    gemm_body_128<false>(g_A, g_A, g_Wo, m0, n0, acc);

    const int lane = threadIdx.x & 31, wid = threadIdx.x >> 5;
    const int wm = wid & 1, wn = wid >> 1;
    #pragma unroll
    for (int mf = 0; mf < 4; ++mf)
        #pragma unroll
        for (int hh = 0; hh < 2; ++hh) {
            int m = m0 + wm*64 + mf*16 + hh*8 + (lane >> 2);
            #pragma unroll
            for (int nf = 0; nf < 4; ++nf) {
                int n = n0 + wn*32 + nf*8 + (lane & 3)*2;
                float2 v = make_float2(acc[mf][nf][hh*2+0] + bo[n],
                                       acc[mf][nf][hh*2+1] + bo[n+1]);
                *(float2*)&out[(size_t)m * EMB + n] = v;
            }
        }
}

// ---------------- flash attention: BQ=128, 8 warps m16, 3-stage, 2 CTA/SM ---
#define ASP     144
#define QL_OFF  18432
#define KV_BASE 36864
#define V_OFF   9216
#define KV_STG  18432
#define ATT_SMEM (KV_BASE + 3*KV_STG)   // 92160

__global__ void __launch_bounds__(256, 2) attn_kernel()
{
    extern __shared__ char sm[];
    const uint32_t smb = smem_u32(sm);
    const int tid = threadIdx.x, lane = tid & 31, w = tid >> 5;
    const int bh = blockIdx.y, q0 = blockIdx.x << 7;

    const __half* Qh = g_Qh + ((size_t)bh*SEQ + q0)*HD;
    const __half* Ql = g_Ql + ((size_t)bh*SEQ + q0)*HD;
    const __half* Kh = g_Kh + (size_t)bh*SEQ*HD;
    const __half* Vh = g_Vh + (size_t)bh*SEQ*HD;

    auto issue_kv = [&](int it) {
        const int kv0 = it << 6;
        const uint32_t sb = smb + KV_BASE + (uint32_t)(it % 3) * KV_STG;
        #pragma unroll
        for (int j = 0; j < 4; ++j) {
            int idx = tid + (j << 8);
            int arr = idx >> 9, c = idx & 511;
            int row = c >> 3, seg = c & 7;
            size_t ga = (size_t)(kv0 + row)*HD + seg*8;
            const __half* g = (arr == 0) ? Kh : Vh;
            cp16(sb + arr*V_OFF + row*ASP + seg*16, g + ga);
        }
        CP_COMMIT();
    };

    // Q: 128 rows x 8 segs x {hi,lo} = 2048 chunks -> 8 per thread
    #pragma unroll
    for (int j = 0; j < 8; ++j) {
        int idx = tid + (j << 8);
        int lo_ = idx >> 10, c = idx & 1023;
        int row = c >> 3, seg = c & 7;
        const __half* g = (lo_ ? Ql : Qh) + (size_t)row*HD + seg*8;
        cp16(smb + (lo_ ? QL_OFF : 0) + row*ASP + seg*16, g);
    }
    CP_COMMIT();
    issue_kv(0);
    issue_kv(1);

    float o[8][4] = {};
    float m0_ = __int_as_float(0xff800000), m1_ = m0_;
    float l0_ = 0.f, l1_ = 0.f;

    for (int it = 0; it < SEQ/64; ++it) {
        if (it + 1 < SEQ/64) CP_WAIT(1); else CP_WAIT(0);
        __syncthreads();
        if (it + 2 < SEQ/64) issue_kv(it + 2);
        const uint32_t kb = smb + KV_BASE + (uint32_t)(it % 3) * KV_STG;

        // S = Q K^T (Q 2-term)
        float s[8][4] = {};
        #pragma unroll
        for (int ks = 0; ks < 4; ++ks) {
            uint32_t aQh[4], aQl[4], bF[4][4];
            uint32_t qrow = w*16 + ((lane>>3)&1)*8 + (lane&7);
            uint32_t qcol = ks*32 + ((lane>>4)&1)*16;
            ldsm4(aQh, smb + qrow*ASP + qcol);
            ldsm4(aQl, smb + QL_OFF + qrow*ASP + qcol);
            #pragma unroll
            for (int ng = 0; ng < 4; ++ng) {
                uint32_t krow = ng*16 + ((lane>>4)&1)*8 + (lane&7);
                uint32_t kcol = ks*32 + ((lane>>3)&1)*16;
                ldsm4(bF[ng], kb + krow*ASP + kcol);
            }
            #pragma unroll
            for (int ng = 0; ng < 4; ++ng) {
                mma_h(s[2*ng],   aQh, bF[ng][0], bF[ng][1]);
                mma_h(s[2*ng+1], aQh, bF[ng][2], bF[ng][3]);
            }
            #pragma unroll
            for (int ng = 0; ng < 4; ++ng) {
                mma_h(s[2*ng],   aQl, bF[ng][0], bF[ng][1]);
                mma_h(s[2*ng+1], aQl, bF[ng][2], bF[ng][3]);
            }
        }

        // online softmax (rows lane>>2 and +8); sums via ones-MMA
        float mx0 = fmaxf(s[0][0], s[0][1]), mx1 = fmaxf(s[0][2], s[0][3]);
        #pragma unroll
        for (int j = 1; j < 8; ++j) {
            mx0 = fmaxf(mx0, fmaxf(s[j][0], s[j][1]));
            mx1 = fmaxf(mx1, fmaxf(s[j][2], s[j][3]));
        }
        mx0 = fmaxf(mx0, __shfl_xor_sync(0xffffffffu, mx0, 1));
        mx0 = fmaxf(mx0, __shfl_xor_sync(0xffffffffu, mx0, 2));
        mx1 = fmaxf(mx1, __shfl_xor_sync(0xffffffffu, mx1, 1));
        mx1 = fmaxf(mx1, __shfl_xor_sync(0xffffffffu, mx1, 2));
        float mn0 = fmaxf(m0_, mx0), mn1 = fmaxf(m1_, mx1);
        float c0 = exp2f(m0_ - mn0), c1 = exp2f(m1_ - mn1);
        m0_ = mn0; m1_ = mn1;
        #pragma unroll
        for (int j = 0; j < 8; ++j) {
            o[j][0] *= c0; o[j][1] *= c0; o[j][2] *= c1; o[j][3] *= c1;
        }

        // O += P V ; l += P @ ones.  P = ex2(s - mn) in fp16x2 directly.
        float lacc[4] = {};
        #pragma unroll
        for (int ks = 0; ks < 4; ++ks) {
            uint32_t aP[4];
            aP[0] = ex2h2(packh(s[2*ks][0]   - mn0, s[2*ks][1]   - mn0));
            aP[1] = ex2h2(packh(s[2*ks][2]   - mn1, s[2*ks][3]   - mn1));
            aP[2] = ex2h2(packh(s[2*ks+1][0] - mn0, s[2*ks+1][1] - mn0));
            aP[3] = ex2h2(packh(s[2*ks+1][2] - mn1, s[2*ks+1][3] - mn1));
            mma_h(lacc, aP, ONESH2, ONESH2);
            #pragma unroll
            for (int ng = 0; ng < 4; ++ng) {
                uint32_t bH[4];
                uint32_t vrow = ks*16 + ((lane>>3)&1)*8 + (lane&7);
                uint32_t vcol = ng*32 + ((lane>>4)&1)*16;
                ldsm4t(bH, kb + V_OFF + vrow*ASP + vcol);
                mma_h(o[2*ng],   aP, bH[0], bH[1]);
                mma_h(o[2*ng+1], aP, bH[2], bH[3]);
            }
        }
        l0_ = l0_ * c0 + lacc[0];
        l1_ = l1_ * c1 + lacc[2];
    }

    // epilogue -> single fp16 A in [B*S][EMB]
    const int b = bh >> 4, h = bh & 15;
    float inv0 = 1.0f / l0_, inv1 = 1.0f / l1_;
    const int r0 = q0 + w*16 + (lane >> 2), r1 = r0 + 8;
    #pragma unroll
    for (int nf = 0; nf < 8; ++nf) {
        int d = nf*8 + (lane & 3)*2;
        int e = h*HD + d;
        *(uint32_t*)(g_A + ((size_t)(b*SEQ + r0))*EMB + e) = packh(o[nf][0]*inv0, o[nf][1]*inv0);
        *(uint32_t*)(g_A + ((size_t)(b*SEQ + r1))*EMB + e) = packh(o[nf][2]*inv1, o[nf][3]*inv1);
    }
}

// ---------------------------------------------------------------------------
extern "C" void kernel_launch(void* const* d_in, const int* in_sizes, int n_in,
                              void* d_out, int out_size)
{
    (void)in_sizes; (void)n_in; (void)out_size;
    const float* x  = (const float*)d_in[0];
    const float* Wq = (const float*)d_in[1];
    const float* bq = (const float*)d_in[2];
    const float* Wk = (const float*)d_in[3];
    const float* bk = (const float*)d_in[4];
    const float* Wv = (const float*)d_in[5];
    const float* bv = (const float*)d_in[6];
    const float* Wo = (const float*)d_in[7];
    const float* bo = (const float*)d_in[8];
    float* out = (float*)d_out;

    cudaFuncSetAttribute(qkv_kernel,     cudaFuncAttributeMaxDynamicSharedMemorySize, GEMM_SMEM);
    cudaFuncSetAttribute(outproj_kernel, cudaFuncAttributeMaxDynamicSharedMemorySize, GEMM_SMEM);
    cudaFuncSetAttribute(attn_kernel,    cudaFuncAttributeMaxDynamicSharedMemorySize, ATT_SMEM);

    split_all_kernel<<<4096, 256>>>(x, Wq, Wk, Wv, Wo);

    dim3 gqkv(EMB/128, MTOK/128, 3);     // 8 x 32 x 3
    qkv_kernel<<<gqkv, 256, GEMM_SMEM>>>(bq, bk, bv);

    dim3 gattn(SEQ/128, BHN);            // 16 x 32
    attn_kernel<<<gattn, 256, ATT_SMEM>>>();

    dim3 gout(EMB/128, MTOK/128);        // 8 x 32
    outproj_kernel<<<gout, 256, GEMM_SMEM>>>(bo, out);
}